// round 12
// baseline (speedup 1.0000x reference)
#include <cuda_runtime.h>
#include <cuda_fp16.h>
#include <cstdint>

// Problem constants
#define BB   16
#define CC   384      // C
#define CO   1536     // EXP*C
#define HW   1024     // 32*32
#define EMB_ 1024
#define NG   32
#define CPG  12
#define EPS_ 1e-5f

// ---------------- scratch (device globals) ---------------------------------
__device__ __align__(16) float  g_A[BB * CC];
__device__ __align__(16) float  g_D[BB * CC];
__device__ __align__(16) float  g_S[BB * CO];
__device__ __align__(16) float  g_T[BB * CO];
__device__ __align__(16) __half g_W1h[CO * CC];                // fp16 w1 [o][c]
__device__ __align__(16) __half g_W2h[CC * CO];                // fp16 w2 [o2][c']
__device__ __align__(16) __half g_Xnh[(size_t)BB * HW * CC];   // fp16 xn^T [b][s][c]
__device__ __align__(16) __half g_Hh[(size_t)BB * HW * CO];    // fp16 hidden [b][s][o]

// ---------------- helpers --------------------------------------------------
__device__ __forceinline__ void cpa16(uint32_t dst, const void* src) {
    asm volatile("cp.async.cg.shared.global [%0], [%1], 16;" :: "r"(dst), "l"(src));
}
#define CP_COMMIT() asm volatile("cp.async.commit_group;")
#define CP_WAITD()  asm volatile("cp.async.wait_group 3;")

#define LDSM4(r0, r1, r2, r3, a)                                               \
    asm volatile("ldmatrix.sync.aligned.m8n8.x4.shared.b16 {%0,%1,%2,%3}, [%4];" \
        : "=r"(r0), "=r"(r1), "=r"(r2), "=r"(r3) : "r"(a))

#define MMA_F16(d, a, b)                                                       \
    asm volatile(                                                              \
        "mma.sync.aligned.m16n8k16.row.col.f32.f16.f16.f32 "                   \
        "{%0,%1,%2,%3},{%4,%5,%6,%7},{%8,%9},{%0,%1,%2,%3};\n"                 \
        : "+f"((d)[0]), "+f"((d)[1]), "+f"((d)[2]), "+f"((d)[3])               \
        : "r"((a)[0]), "r"((a)[1]), "r"((a)[2]), "r"((a)[3]),                  \
          "r"((b)[0]), "r"((b)[1]))

// ---------------------------------------------------------------------------
// K_setup: FUSED gnstats + emb + w->fp16 prep + out-init, by blockIdx range.
//   blocks [0, 512):      GroupNorm stats -> (A, D)
//   blocks [512, 896):    emb_out = emb @ we.T + be -> S, T
//   blocks [896, 2048):   w1/w2 -> fp16
//   blocks [2048, 8192):  out = x + b2   (split-K gemm2 accumulates into it)
// ---------------------------------------------------------------------------
__global__ void __launch_bounds__(256)
k_setup(const float* __restrict__ x,
        const float* __restrict__ gnw,
        const float* __restrict__ gnb,
        const float* __restrict__ emb,
        const float* __restrict__ we,
        const float* __restrict__ be,
        const float* __restrict__ w1,
        const float* __restrict__ w2,
        const float* __restrict__ b2,
        float* __restrict__ out) {
    int bid = blockIdx.x;
    if (bid < 512) {
        // ---- GroupNorm stats ----
        int b = bid >> 5;
        int gi = bid & 31;
        const float4* p = (const float4*)(x + ((size_t)b * CC + (size_t)gi * CPG) * HW);
        float s = 0.f, ss = 0.f;
#pragma unroll
        for (int i = 0; i < 12; i++) {
            float4 v = p[threadIdx.x + i * 256];
            s  += v.x + v.y + v.z + v.w;
            ss += v.x * v.x + v.y * v.y + v.z * v.z + v.w * v.w;
        }
#pragma unroll
        for (int off = 16; off; off >>= 1) {
            s  += __shfl_xor_sync(0xffffffffu, s, off);
            ss += __shfl_xor_sync(0xffffffffu, ss, off);
        }
        __shared__ float sh[64];
        int w = threadIdx.x >> 5, l = threadIdx.x & 31;
        if (l == 0) { sh[w] = s; sh[32 + w] = ss; }
        __syncthreads();
        if (threadIdx.x < CPG) {
            float S = 0.f, SS = 0.f;
#pragma unroll
            for (int i = 0; i < 8; i++) { S += sh[i]; SS += sh[32 + i]; }
            float mean = S * (1.0f / 12288.0f);
            float var  = SS * (1.0f / 12288.0f) - mean * mean;
            float rstd = rsqrtf(var + EPS_);
            int cch = gi * CPG + threadIdx.x;
            float wv = gnw[cch], bv = gnb[cch];
            g_A[b * CC + cch] = rstd * wv;
            g_D[b * CC + cch] = bv - mean * rstd * wv;
        }
    } else if (bid < 896) {
        // ---- emb GEMV: one warp per output row o, all 16 batches ----
        int o = (bid - 512) * 8 + (threadIdx.x >> 5);   // 0..3071
        int lane = threadIdx.x & 31;
        const float4* w4 = (const float4*)(we + (size_t)o * EMB_);
        float4 wv[8];
#pragma unroll
        for (int i = 0; i < 8; i++) wv[i] = w4[lane + i * 32];
        float bev = be[o];

        float mine = 0.f;
#pragma unroll
        for (int b = 0; b < BB; b++) {
            const float4* e4 = (const float4*)(emb + (size_t)b * EMB_);
            float s = 0.f;
#pragma unroll
            for (int i = 0; i < 8; i++) {
                float4 ev = e4[lane + i * 32];
                s += ev.x * wv[i].x + ev.y * wv[i].y + ev.z * wv[i].z + ev.w * wv[i].w;
            }
#pragma unroll
            for (int off = 16; off; off >>= 1)
                s += __shfl_xor_sync(0xffffffffu, s, off);
            if (lane == b) mine = s;
        }
        if (lane < BB) {
            if (o < CO) g_S[lane * CO + o] = 1.0f + mine + bev;
            else        g_T[lane * CO + (o - CO)] = mine + bev;
        }
    } else if (bid < 2048) {
        // ---- weights -> fp16 ----
        const int N1 = CO * CC / 4;
        int t = (bid - 896) * 256 + threadIdx.x;
        const float4* src = (t < N1) ? (const float4*)w1 : (const float4*)w2;
        int i = (t < N1) ? t : t - N1;
        float4 v = src[i];
        __half2 lo = __floats2half2_rn(v.x, v.y);
        __half2 hi = __floats2half2_rn(v.z, v.w);
        uint2 pk = make_uint2(*(uint32_t*)&lo, *(uint32_t*)&hi);
        if (t < N1) ((uint2*)g_W1h)[i] = pk;
        else        ((uint2*)g_W2h)[i] = pk;
    } else {
        // ---- out init: out[b][o2][s] = x[b][o2][s] + b2[o2] ----
        int t = (bid - 2048) * 256 + threadIdx.x;       // float4 index
        float bv = b2[(t >> 8) % CC];                   // HW/4 = 256 f4 per row
        float4 v = ((const float4*)x)[t];
        v.x += bv; v.y += bv; v.z += bv; v.w += bv;
        ((float4*)out)[t] = v;
    }
}

// ---------------------------------------------------------------------------
// K_norm_t: xn^T = fp16(A*x + D), transposed to [b][s][c]  (64x64 smem tiles)
// ---------------------------------------------------------------------------
__global__ void k_norm_t(const float* __restrict__ x) {
    __shared__ float sm[64][65];
    int b = blockIdx.z;
    int cg = blockIdx.y * 64;
    int sg = blockIdx.x * 64;
    int tid = threadIdx.x;
    int r = tid >> 2, q = tid & 3;
    float a = g_A[b * CC + cg + r];
    float d = g_D[b * CC + cg + r];
    const float* xr = x + ((size_t)b * CC + cg + r) * HW + sg + q * 16;
#pragma unroll
    for (int i = 0; i < 4; i++) {
        float4 v = *(const float4*)(xr + i * 4);
        sm[r][q * 16 + i * 4 + 0] = fmaf(a, v.x, d);
        sm[r][q * 16 + i * 4 + 1] = fmaf(a, v.y, d);
        sm[r][q * 16 + i * 4 + 2] = fmaf(a, v.z, d);
        sm[r][q * 16 + i * 4 + 3] = fmaf(a, v.w, d);
    }
    __syncthreads();
    __half* orow = g_Xnh + ((size_t)b * HW + sg + r) * CC + cg + q * 16;
#pragma unroll
    for (int i = 0; i < 4; i++) {
        __half2 lo = __floats2half2_rn(sm[q*16+i*4+0][r], sm[q*16+i*4+1][r]);
        __half2 hi = __floats2half2_rn(sm[q*16+i*4+2][r], sm[q*16+i*4+3][r]);
        *(uint2*)(orow + i * 4) = make_uint2(*(uint32_t*)&lo, *(uint32_t*)&hi);
    }
}

// ---------------------------------------------------------------------------
// GEMM core: CTA tile 128x128, BK=32 fp16, FIVE-stage cp.async ring.
// One barrier per k-tile (ordering proven R9/R11):
//   CP_WAITD(wait_group 3) -> __syncthreads -> fill((kt+4)%5) -> commit
//   -> compute(kt%5)
// ---------------------------------------------------------------------------
#define ROWPITCH 80
#define TILE_B   (128 * ROWPITCH)      // 10240 B per operand tile
#define STG_B    (2 * TILE_B)          // 20480 B per stage
#define NSTAGE   5
#define SMEM_BYTES (NSTAGE * STG_B)    // 102400 B

extern __shared__ uint8_t dsm8[];

__device__ __forceinline__ void fill_stage(uint32_t sdst,
        const __half* Asrc, size_t lda, const __half* Bsrc, size_t ldb, int tid) {
#pragma unroll
    for (int i = 0; i < 4; i++) {
        int ch = tid + i * 256;            // 0..1023
        int isB = ch >> 9;                 // 512 chunks per operand
        int r   = (ch & 511) >> 2;
        int cb  = ch & 3;
        const __half* src = isB ? (Bsrc + (size_t)r * ldb + cb * 8)
                                : (Asrc + (size_t)r * lda + cb * 8);
        cpa16(sdst + isB * TILE_B + r * ROWPITCH + cb * 16, src);
    }
}

template <int KT>
__device__ __forceinline__ void gemm_mainloop(
        const __half* Abase, size_t lda, const __half* Bbase, size_t ldb,
        float acc[2][8][4], int tid) {
    const int lane = tid & 31, warp = tid >> 5;
    const int wm = warp & 3, wn = warp >> 2;
#pragma unroll
    for (int i = 0; i < 2; i++)
#pragma unroll
        for (int j = 0; j < 8; j++)
#pragma unroll
            for (int e = 0; e < 4; e++) acc[i][j][e] = 0.f;

    uint32_t smb = (uint32_t)__cvta_generic_to_shared(dsm8);
    uint32_t aoff = (uint32_t)((wm * 32 + (lane & 15)) * ROWPITCH + (lane >> 4) * 16);
    uint32_t boff = (uint32_t)((wn * 64 + (lane & 7) + ((lane >> 4) << 3)) * ROWPITCH
                               + ((lane >> 3) & 1) * 16);

    // prologue: stages 0..3 (commits #1..#4)
#pragma unroll
    for (int s = 0; s < NSTAGE - 1; s++) {
        fill_stage(smb + s * STG_B, Abase + s * 32, lda, Bbase + s * 32, ldb, tid);
        CP_COMMIT();
    }

    int s_cur = 0;                 // ring index of stage kt
    int s_fill = NSTAGE - 1;       // ring index of stage kt+4
    for (int kt = 0; kt < KT; kt++) {
        // commits before wait: 4 + kt; pending <= 3 => stage kt landed (thread)
        CP_WAITD();
        __syncthreads();   // publish stage kt; readers of stage kt-1 all done

        if (kt + NSTAGE - 1 < KT)
            fill_stage(smb + s_fill * STG_B,
                       Abase + (size_t)(kt + NSTAGE - 1) * 32, lda,
                       Bbase + (size_t)(kt + NSTAGE - 1) * 32, ldb, tid);
        CP_COMMIT();       // commit every iter (empty ok) keeps the count exact

        uint32_t sA = smb + s_cur * STG_B;
        uint32_t sB = sA + TILE_B;
#pragma unroll
        for (int kk = 0; kk < 2; kk++) {           // two k16 chunks
            uint32_t af[2][4], bf[8][2];
#pragma unroll
            for (int mt = 0; mt < 2; mt++)
                LDSM4(af[mt][0], af[mt][1], af[mt][2], af[mt][3],
                      sA + aoff + mt * 16 * ROWPITCH + kk * 32);
#pragma unroll
            for (int p = 0; p < 4; p++) {
                uint32_t r0, r1, r2, r3;
                LDSM4(r0, r1, r2, r3, sB + boff + p * 16 * ROWPITCH + kk * 32);
                bf[2 * p][0] = r0;  bf[2 * p][1] = r1;
                bf[2 * p + 1][0] = r2; bf[2 * p + 1][1] = r3;
            }
#pragma unroll
            for (int mt = 0; mt < 2; mt++)
#pragma unroll
                for (int nt = 0; nt < 8; nt++)
                    MMA_F16(acc[mt][nt], af[mt], bf[nt]);
        }
        s_cur  = (s_cur  == NSTAGE - 1) ? 0 : s_cur + 1;
        s_fill = (s_fill == NSTAGE - 1) ? 0 : s_fill + 1;
    }
}

// ---------------------------------------------------------------------------
// K_gemm1: D[s,o] = xn^T[s,c] @ w1[o,c]^T; M=s,N=o,K=CC.
// epilogue: +b1, silu, *(1+scale)+shift -> H[b][s][o] fp16
// ---------------------------------------------------------------------------
__global__ void __launch_bounds__(256, 2)
k_gemm1(const float* __restrict__ b1) {
    __shared__ float sb1[128], sS[128], sT[128];
    const int tid = threadIdx.x;
    const int b = blockIdx.z;
    const int o0 = blockIdx.y * 128;
    const int s0 = blockIdx.x * 128;
    if (tid < 128) {
        int o = o0 + tid;
        sb1[tid] = b1[o];
        sS[tid]  = g_S[b * CO + o];
        sT[tid]  = g_T[b * CO + o];
    }
    __syncthreads();

    const __half* Abase = g_Xnh + ((size_t)b * HW + s0) * CC;
    const __half* Bbase = g_W1h + (size_t)o0 * CC;
    float acc[2][8][4];
    gemm_mainloop<CC / 32>(Abase, CC, Bbase, CC, acc, tid);

    const int lane = tid & 31, warp = tid >> 5;
    const int wm = warp & 3, wn = warp >> 2;
    const int g = lane >> 2, t = lane & 3;
    __half* Hb = g_Hh + ((size_t)b * HW + s0) * CO + o0;
#pragma unroll
    for (int mt = 0; mt < 2; mt++)
#pragma unroll
        for (int h = 0; h < 2; h++) {
            int s_loc = wm * 32 + mt * 16 + h * 8 + g;
            __half* Hrow = Hb + (size_t)s_loc * CO;
#pragma unroll
            for (int nt = 0; nt < 8; nt++) {
                int oc = wn * 64 + nt * 8 + t * 2;
                float v0 = acc[mt][nt][h * 2 + 0] + sb1[oc];
                float v1 = acc[mt][nt][h * 2 + 1] + sb1[oc + 1];
                float h0 = v0 / (1.0f + __expf(-v0));
                float h1 = v1 / (1.0f + __expf(-v1));
                __half2 pk = __floats2half2_rn(h0 * sS[oc] + sT[oc],
                                               h1 * sS[oc + 1] + sT[oc + 1]);
                *(uint32_t*)(Hrow + oc) = *(uint32_t*)&pk;
            }
        }
}

// ---------------------------------------------------------------------------
// K_gemm2: SPLIT-K=2. D[o2,s] += w2[o2, kh*768 + c'] @ H[s, kh*768 + c']^T.
// Same 128x128 CTA tile (fill/MMA ratio preserved); grid 384 -> 768 CTAs
// kills the 1.3-wave tail (2 waves @65% -> 3 waves @86%).
// out preallocated to x + b2 by k_setup; contributions via atomicAdd (RED).
// ---------------------------------------------------------------------------
__global__ void __launch_bounds__(256, 2)
k_gemm2(const float* __restrict__ x,
        float* __restrict__ out) {
    const int tid = threadIdx.x;
    const int b = blockIdx.z;
    const int o20 = (blockIdx.y % 3) * 128;
    const int kh  = blockIdx.y / 3;            // 0 or 1
    const int s0 = blockIdx.x * 128;

    const __half* Abase = g_W2h + (size_t)o20 * CO + (size_t)kh * (CO / 2);
    const __half* Bbase = g_Hh + ((size_t)b * HW + s0) * CO + (size_t)kh * (CO / 2);
    float acc[2][8][4];
    gemm_mainloop<CO / 64>(Abase, CO, Bbase, CO, acc, tid);   // KT = 24

    const int lane = tid & 31, warp = tid >> 5;
    const int wm = warp & 3, wn = warp >> 2;
    const int g = lane >> 2, t = lane & 3;
#pragma unroll
    for (int mt = 0; mt < 2; mt++)
#pragma unroll
        for (int h = 0; h < 2; h++) {
            int o2 = o20 + wm * 32 + mt * 16 + h * 8 + g;
            float* orow = out + (size_t)b * CC * HW + (size_t)o2 * HW + s0;
#pragma unroll
            for (int nt = 0; nt < 8; nt++) {
                int sc = wn * 64 + nt * 8 + t * 2;
                atomicAdd(orow + sc,     acc[mt][nt][h * 2 + 0]);
                atomicAdd(orow + sc + 1, acc[mt][nt][h * 2 + 1]);
            }
        }
}

// ---------------------------------------------------------------------------
extern "C" void kernel_launch(void* const* d_in, const int* in_sizes, int n_in,
                              void* d_out, int out_size) {
    const float* x    = (const float*)d_in[0];
    const float* emb  = (const float*)d_in[1];
    const float* gn_w = (const float*)d_in[2];
    const float* gn_b = (const float*)d_in[3];
    const float* w1   = (const float*)d_in[4];
    const float* b1   = (const float*)d_in[5];
    const float* we   = (const float*)d_in[6];
    const float* be   = (const float*)d_in[7];
    const float* w2   = (const float*)d_in[8];
    const float* b2   = (const float*)d_in[9];
    float* out = (float*)d_out;

    static bool attr_set = false;
    if (!attr_set) {
        cudaFuncSetAttribute(k_gemm1, cudaFuncAttributeMaxDynamicSharedMemorySize, SMEM_BYTES);
        cudaFuncSetAttribute(k_gemm2, cudaFuncAttributeMaxDynamicSharedMemorySize, SMEM_BYTES);
        attr_set = true;
    }

    // setup: 512 gnstats + 384 emb + 1152 prep + 6144 out-init blocks
    k_setup<<<8192, 256>>>(x, gn_w, gn_b, emb, we, be, w1, w2, b2, out);
    k_norm_t<<<dim3(HW / 64, CC / 64, BB), 256>>>(x);
    k_gemm1<<<dim3(HW / 128, CO / 128, BB), 256, SMEM_BYTES>>>(b1);
    k_gemm2<<<dim3(HW / 128, 6, BB), 256, SMEM_BYTES>>>(x, out);
}

// round 13
// speedup vs baseline: 1.1102x; 1.1102x over previous
#include <cuda_runtime.h>
#include <cuda_fp16.h>
#include <cstdint>

// Problem constants
#define BB   16
#define CC   384      // C
#define CO   1536     // EXP*C
#define HW   1024     // 32*32
#define EMB_ 1024
#define NG   32
#define CPG  12
#define EPS_ 1e-5f

// ---------------- scratch (device globals) ---------------------------------
__device__ __align__(16) float  g_A[BB * CC];
__device__ __align__(16) float  g_D[BB * CC];
__device__ __align__(16) float  g_S[BB * CO];
__device__ __align__(16) float  g_T[BB * CO];
__device__ __align__(16) float  g_B1[BB * CO];                 // b1 + w1 @ D (fp32)
__device__ __align__(16) __half g_W1h[CO * CC];                // fp16 w1 [o][c]
__device__ __align__(16) __half g_W2h[CC * CO];                // fp16 w2 [o2][c']
__device__ __align__(16) __half g_Xh[(size_t)BB * CC * HW];    // fp16 a*x, NATURAL [b][c][s]
__device__ __align__(16) __half g_Hh[(size_t)BB * HW * CO];    // fp16 hidden [b][s][o]

// ---------------- helpers --------------------------------------------------
__device__ __forceinline__ void cpa16(uint32_t dst, const void* src) {
    asm volatile("cp.async.cg.shared.global [%0], [%1], 16;" :: "r"(dst), "l"(src));
}
#define CP_COMMIT() asm volatile("cp.async.commit_group;")
#define CP_WAITD()  asm volatile("cp.async.wait_group 3;")

#define LDSM4(r0, r1, r2, r3, a)                                               \
    asm volatile("ldmatrix.sync.aligned.m8n8.x4.shared.b16 {%0,%1,%2,%3}, [%4];" \
        : "=r"(r0), "=r"(r1), "=r"(r2), "=r"(r3) : "r"(a))

#define LDSM4T(r0, r1, r2, r3, a)                                              \
    asm volatile("ldmatrix.sync.aligned.m8n8.x4.trans.shared.b16 {%0,%1,%2,%3}, [%4];" \
        : "=r"(r0), "=r"(r1), "=r"(r2), "=r"(r3) : "r"(a))

#define MMA_F16(d, a, b)                                                       \
    asm volatile(                                                              \
        "mma.sync.aligned.m16n8k16.row.col.f32.f16.f16.f32 "                   \
        "{%0,%1,%2,%3},{%4,%5,%6,%7},{%8,%9},{%0,%1,%2,%3};\n"                 \
        : "+f"((d)[0]), "+f"((d)[1]), "+f"((d)[2]), "+f"((d)[3])               \
        : "r"((a)[0]), "r"((a)[1]), "r"((a)[2]), "r"((a)[3]),                  \
          "r"((b)[0]), "r"((b)[1]))

// ---------------------------------------------------------------------------
// K_setup: FUSED gnstats + emb + w->fp16 prep (R11 config, proven).
//   blocks [0, 512):    GroupNorm stats -> (A, D)
//   blocks [512, 896):  emb_out = emb @ we.T + be -> S, T
//   blocks [896, 2048): w1/w2 -> fp16
// ---------------------------------------------------------------------------
__global__ void __launch_bounds__(256)
k_setup(const float* __restrict__ x,
        const float* __restrict__ gnw,
        const float* __restrict__ gnb,
        const float* __restrict__ emb,
        const float* __restrict__ we,
        const float* __restrict__ be,
        const float* __restrict__ w1,
        const float* __restrict__ w2) {
    int bid = blockIdx.x;
    if (bid < 512) {
        int b = bid >> 5;
        int gi = bid & 31;
        const float4* p = (const float4*)(x + ((size_t)b * CC + (size_t)gi * CPG) * HW);
        float s = 0.f, ss = 0.f;
#pragma unroll
        for (int i = 0; i < 12; i++) {
            float4 v = p[threadIdx.x + i * 256];
            s  += v.x + v.y + v.z + v.w;
            ss += v.x * v.x + v.y * v.y + v.z * v.z + v.w * v.w;
        }
#pragma unroll
        for (int off = 16; off; off >>= 1) {
            s  += __shfl_xor_sync(0xffffffffu, s, off);
            ss += __shfl_xor_sync(0xffffffffu, ss, off);
        }
        __shared__ float sh[64];
        int w = threadIdx.x >> 5, l = threadIdx.x & 31;
        if (l == 0) { sh[w] = s; sh[32 + w] = ss; }
        __syncthreads();
        if (threadIdx.x < CPG) {
            float S = 0.f, SS = 0.f;
#pragma unroll
            for (int i = 0; i < 8; i++) { S += sh[i]; SS += sh[32 + i]; }
            float mean = S * (1.0f / 12288.0f);
            float var  = SS * (1.0f / 12288.0f) - mean * mean;
            float rstd = rsqrtf(var + EPS_);
            int cch = gi * CPG + threadIdx.x;
            float wv = gnw[cch], bv = gnb[cch];
            g_A[b * CC + cch] = rstd * wv;
            g_D[b * CC + cch] = bv - mean * rstd * wv;
        }
    } else if (bid < 896) {
        int o = (bid - 512) * 8 + (threadIdx.x >> 5);   // 0..3071
        int lane = threadIdx.x & 31;
        const float4* w4 = (const float4*)(we + (size_t)o * EMB_);
        float4 wv[8];
#pragma unroll
        for (int i = 0; i < 8; i++) wv[i] = w4[lane + i * 32];
        float bev = be[o];

        float mine = 0.f;
#pragma unroll
        for (int b = 0; b < BB; b++) {
            const float4* e4 = (const float4*)(emb + (size_t)b * EMB_);
            float s = 0.f;
#pragma unroll
            for (int i = 0; i < 8; i++) {
                float4 ev = e4[lane + i * 32];
                s += ev.x * wv[i].x + ev.y * wv[i].y + ev.z * wv[i].z + ev.w * wv[i].w;
            }
#pragma unroll
            for (int off = 16; off; off >>= 1)
                s += __shfl_xor_sync(0xffffffffu, s, off);
            if (lane == b) mine = s;
        }
        if (lane < BB) {
            if (o < CO) g_S[lane * CO + o] = 1.0f + mine + bev;
            else        g_T[lane * CO + (o - CO)] = mine + bev;
        }
    } else {
        const int N1 = CO * CC / 4;
        int t = (bid - 896) * 256 + threadIdx.x;
        const float4* src = (t < N1) ? (const float4*)w1 : (const float4*)w2;
        int i = (t < N1) ? t : t - N1;
        float4 v = src[i];
        __half2 lo = __floats2half2_rn(v.x, v.y);
        __half2 hi = __floats2half2_rn(v.z, v.w);
        uint2 pk = make_uint2(*(uint32_t*)&lo, *(uint32_t*)&hi);
        if (t < N1) ((uint2*)g_W1h)[i] = pk;
        else        ((uint2*)g_W2h)[i] = pk;
    }
}

// ---------------------------------------------------------------------------
// K_fold (replaces norm_t): depends on g_A/g_D from k_setup.
//   blocks [0, 192):     b1'[b,o] = b1[o] + sum_c w1[o,c]*D[b,c] (fp32)
//   blocks [192, 1728):  xh[b][c][s] = fp16(A[b,c] * x[b,c,s])  (streaming)
// ---------------------------------------------------------------------------
__global__ void __launch_bounds__(256)
k_fold(const float* __restrict__ w1,
       const float* __restrict__ b1,
       const float* __restrict__ x) {
    int bid = blockIdx.x;
    if (bid < 192) {
        // ---- bias fold: warp per o, w1 row in registers, loop batches ----
        int o = bid * 8 + (threadIdx.x >> 5);       // 0..1535
        int lane = threadIdx.x & 31;
        const float4* w4 = (const float4*)(w1 + (size_t)o * CC);
        float4 wv[3];
#pragma unroll
        for (int i = 0; i < 3; i++) wv[i] = w4[lane + i * 32];
        float bv = b1[o];
        float mine = 0.f;
#pragma unroll
        for (int b = 0; b < BB; b++) {
            const float* dr = g_D + b * CC;
            float s = 0.f;
#pragma unroll
            for (int i = 0; i < 3; i++) {
                int c = (lane + i * 32) * 4;
                s += wv[i].x * dr[c] + wv[i].y * dr[c + 1]
                   + wv[i].z * dr[c + 2] + wv[i].w * dr[c + 3];
            }
#pragma unroll
            for (int off = 16; off; off >>= 1)
                s += __shfl_xor_sync(0xffffffffu, s, off);
            if (lane == b) mine = s;
        }
        if (lane < BB) g_B1[lane * CO + o] = bv + mine;
    } else {
        // ---- convert-scale: 4 float4 per thread, coalesced ----
        int base = (bid - 192) * 1024 + threadIdx.x;
#pragma unroll
        for (int i = 0; i < 4; i++) {
            int idx = base + i * 256;               // float4 index
            float a = g_A[idx >> 8];                // 256 f4 per (b,c) row
            float4 v = ((const float4*)x)[idx];
            __half2 lo = __floats2half2_rn(a * v.x, a * v.y);
            __half2 hi = __floats2half2_rn(a * v.z, a * v.w);
            ((uint2*)g_Xh)[idx] = make_uint2(*(uint32_t*)&lo, *(uint32_t*)&hi);
        }
    }
}

// ---------------------------------------------------------------------------
// Shared constants. gemm2 keeps the proven R11 geometry exactly.
// ---------------------------------------------------------------------------
#define ROWPITCH 80
#define TILE_B   (128 * ROWPITCH)      // 10240 B (K-major operand tile)
#define STG_B    (2 * TILE_B)          // gemm2 stage
#define NSTAGE   5
#define SMEM2_BYTES (NSTAGE * STG_B)   // 102400 B

// gemm1 A-tile: xh rows are k=c (32), cols m=s (128 halves = 256B), pitch 272
#define PITCH_A1 272
#define TILE_A1  (32 * PITCH_A1)       // 8704 B
#define STG1_B   (TILE_A1 + TILE_B)    // 18944 B
#define SMEM1_BYTES (NSTAGE * STG1_B)  // 94720 B

extern __shared__ uint8_t dsm8[];

// ---- gemm2 fill + mainloop (identical to R11) ----
__device__ __forceinline__ void fill_stage(uint32_t sdst,
        const __half* Asrc, size_t lda, const __half* Bsrc, size_t ldb, int tid) {
#pragma unroll
    for (int i = 0; i < 4; i++) {
        int ch = tid + i * 256;
        int isB = ch >> 9;
        int r   = (ch & 511) >> 2;
        int cb  = ch & 3;
        const __half* src = isB ? (Bsrc + (size_t)r * ldb + cb * 8)
                                : (Asrc + (size_t)r * lda + cb * 8);
        cpa16(sdst + isB * TILE_B + r * ROWPITCH + cb * 16, src);
    }
}

template <int KT>
__device__ __forceinline__ void gemm_mainloop(
        const __half* Abase, size_t lda, const __half* Bbase, size_t ldb,
        float acc[2][8][4], int tid) {
    const int lane = tid & 31, warp = tid >> 5;
    const int wm = warp & 3, wn = warp >> 2;
#pragma unroll
    for (int i = 0; i < 2; i++)
#pragma unroll
        for (int j = 0; j < 8; j++)
#pragma unroll
            for (int e = 0; e < 4; e++) acc[i][j][e] = 0.f;

    uint32_t smb = (uint32_t)__cvta_generic_to_shared(dsm8);
    uint32_t aoff = (uint32_t)((wm * 32 + (lane & 15)) * ROWPITCH + (lane >> 4) * 16);
    uint32_t boff = (uint32_t)((wn * 64 + (lane & 7) + ((lane >> 4) << 3)) * ROWPITCH
                               + ((lane >> 3) & 1) * 16);

#pragma unroll
    for (int s = 0; s < NSTAGE - 1; s++) {
        fill_stage(smb + s * STG_B, Abase + s * 32, lda, Bbase + s * 32, ldb, tid);
        CP_COMMIT();
    }

    int s_cur = 0, s_fill = NSTAGE - 1;
    for (int kt = 0; kt < KT; kt++) {
        CP_WAITD();
        __syncthreads();

        if (kt + NSTAGE - 1 < KT)
            fill_stage(smb + s_fill * STG_B,
                       Abase + (size_t)(kt + NSTAGE - 1) * 32, lda,
                       Bbase + (size_t)(kt + NSTAGE - 1) * 32, ldb, tid);
        CP_COMMIT();

        uint32_t sA = smb + s_cur * STG_B;
        uint32_t sB = sA + TILE_B;
#pragma unroll
        for (int kk = 0; kk < 2; kk++) {
            uint32_t af[2][4], bf[8][2];
#pragma unroll
            for (int mt = 0; mt < 2; mt++)
                LDSM4(af[mt][0], af[mt][1], af[mt][2], af[mt][3],
                      sA + aoff + mt * 16 * ROWPITCH + kk * 32);
#pragma unroll
            for (int p = 0; p < 4; p++) {
                uint32_t r0, r1, r2, r3;
                LDSM4(r0, r1, r2, r3, sB + boff + p * 16 * ROWPITCH + kk * 32);
                bf[2 * p][0] = r0;  bf[2 * p][1] = r1;
                bf[2 * p + 1][0] = r2; bf[2 * p + 1][1] = r3;
            }
#pragma unroll
            for (int mt = 0; mt < 2; mt++)
#pragma unroll
                for (int nt = 0; nt < 8; nt++)
                    MMA_F16(acc[mt][nt], af[mt], bf[nt]);
        }
        s_cur  = (s_cur  == NSTAGE - 1) ? 0 : s_cur + 1;
        s_fill = (s_fill == NSTAGE - 1) ? 0 : s_fill + 1;
    }
}

// ---------------------------------------------------------------------------
// K_gemm1: D[s,o] = xh^T @ w1^T via trans-ldmatrix A (xh in natural [c][s]).
// M=s(128 via A-cols), N=o(128), K=CC. Bias = g_B1[b][o] (fp32 GN-fold).
// epilogue: silu, *(1+scale)+shift -> H[b][s][o] fp16
// ---------------------------------------------------------------------------
__device__ __forceinline__ void fill_g1(uint32_t sdst,
        const __half* Ax, const __half* Bw, int tid) {
#pragma unroll
    for (int i = 0; i < 4; i++) {
        int ch = tid + i * 256;                 // 0..1023
        if (ch < 512) {                         // A: 32 k-rows x 16 chunks
            int r = ch >> 4, cb = ch & 15;
            cpa16(sdst + r * PITCH_A1 + cb * 16, Ax + (size_t)r * HW + cb * 8);
        } else {                                // B: 128 o-rows x 4 chunks
            int base = ch - 512;
            int r = base >> 2, cb = base & 3;
            cpa16(sdst + TILE_A1 + r * ROWPITCH + cb * 16,
                  Bw + (size_t)r * CC + cb * 8);
        }
    }
}

__global__ void __launch_bounds__(256, 2)
k_gemm1() {
    __shared__ float sb1[128], sS[128], sT[128];
    const int tid = threadIdx.x;
    const int b = blockIdx.z;
    const int o0 = blockIdx.y * 128;
    const int s0 = blockIdx.x * 128;
    if (tid < 128) {
        int o = o0 + tid;
        sb1[tid] = g_B1[b * CO + o];
        sS[tid]  = g_S[b * CO + o];
        sT[tid]  = g_T[b * CO + o];
    }
    __syncthreads();

    const __half* Abase = g_Xh + (size_t)b * CC * HW + s0;   // rows k=c, step 32*HW/kt
    const __half* Bbase = g_W1h + (size_t)o0 * CC;

    const int lane = tid & 31, warp = tid >> 5;
    const int wm = warp & 3, wn = warp >> 2;
    float acc[2][8][4];
#pragma unroll
    for (int i = 0; i < 2; i++)
#pragma unroll
        for (int j = 0; j < 8; j++)
#pragma unroll
            for (int e = 0; e < 4; e++) acc[i][j][e] = 0.f;

    uint32_t smb = (uint32_t)__cvta_generic_to_shared(dsm8);
    // trans-A per-lane offset: krow = (lane&7)+((lane>>4)<<3), m-block = (lane>>3)&1
    uint32_t aoff = (uint32_t)(((lane & 7) + ((lane >> 4) << 3)) * PITCH_A1
                               + ((lane >> 3) & 1) * 16);
    uint32_t boff = (uint32_t)((wn * 64 + (lane & 7) + ((lane >> 4) << 3)) * ROWPITCH
                               + ((lane >> 3) & 1) * 16);

    const int KT = CC / 32;   // 12
#pragma unroll
    for (int s = 0; s < NSTAGE - 1; s++) {
        fill_g1(smb + s * STG1_B, Abase + (size_t)s * 32 * HW, Bbase + s * 32, tid);
        CP_COMMIT();
    }

    int s_cur = 0, s_fill = NSTAGE - 1;
    for (int kt = 0; kt < KT; kt++) {
        CP_WAITD();
        __syncthreads();

        if (kt + NSTAGE - 1 < KT)
            fill_g1(smb + s_fill * STG1_B,
                    Abase + (size_t)(kt + NSTAGE - 1) * 32 * HW,
                    Bbase + (size_t)(kt + NSTAGE - 1) * 32, tid);
        CP_COMMIT();

        uint32_t sA = smb + s_cur * STG1_B;
        uint32_t sB = sA + TILE_A1;
#pragma unroll
        for (int kk = 0; kk < 2; kk++) {
            uint32_t af[2][4], bf[8][2];
#pragma unroll
            for (int mt = 0; mt < 2; mt++)
                LDSM4T(af[mt][0], af[mt][1], af[mt][2], af[mt][3],
                       sA + aoff + kk * 16 * PITCH_A1 + (wm * 32 + mt * 16) * 2);
#pragma unroll
            for (int p = 0; p < 4; p++) {
                uint32_t r0, r1, r2, r3;
                LDSM4(r0, r1, r2, r3, sB + boff + p * 16 * ROWPITCH + kk * 32);
                bf[2 * p][0] = r0;  bf[2 * p][1] = r1;
                bf[2 * p + 1][0] = r2; bf[2 * p + 1][1] = r3;
            }
#pragma unroll
            for (int mt = 0; mt < 2; mt++)
#pragma unroll
                for (int nt = 0; nt < 8; nt++)
                    MMA_F16(acc[mt][nt], af[mt], bf[nt]);
        }
        s_cur  = (s_cur  == NSTAGE - 1) ? 0 : s_cur + 1;
        s_fill = (s_fill == NSTAGE - 1) ? 0 : s_fill + 1;
    }

    const int g = lane >> 2, t = lane & 3;
    __half* Hb = g_Hh + ((size_t)b * HW + s0) * CO + o0;
#pragma unroll
    for (int mt = 0; mt < 2; mt++)
#pragma unroll
        for (int h = 0; h < 2; h++) {
            int s_loc = wm * 32 + mt * 16 + h * 8 + g;
            __half* Hrow = Hb + (size_t)s_loc * CO;
#pragma unroll
            for (int nt = 0; nt < 8; nt++) {
                int oc = wn * 64 + nt * 8 + t * 2;
                float v0 = acc[mt][nt][h * 2 + 0] + sb1[oc];
                float v1 = acc[mt][nt][h * 2 + 1] + sb1[oc + 1];
                float h0 = v0 / (1.0f + __expf(-v0));
                float h1 = v1 / (1.0f + __expf(-v1));
                __half2 pk = __floats2half2_rn(h0 * sS[oc] + sT[oc],
                                               h1 * sS[oc + 1] + sT[oc + 1]);
                *(uint32_t*)(Hrow + oc) = *(uint32_t*)&pk;
            }
        }
}

// ---------------------------------------------------------------------------
// K_gemm2: D[o2,s] = w2 @ H^T; M=o2,N=s,K=CO.  Exact R11 config (measured
// best; split-K and 64-wide tiles both measured worse — do not revisit).
// ---------------------------------------------------------------------------
__global__ void __launch_bounds__(256, 2)
k_gemm2(const float* __restrict__ b2,
        const float* __restrict__ x,
        float* __restrict__ out) {
    __shared__ float sb2[128];
    const int tid = threadIdx.x;
    const int b = blockIdx.z;
    const int o20 = blockIdx.y * 128;
    const int s0 = blockIdx.x * 128;
    if (tid < 128) sb2[tid] = b2[o20 + tid];
    __syncthreads();

    const __half* Abase = g_W2h + (size_t)o20 * CO;
    const __half* Bbase = g_Hh + ((size_t)b * HW + s0) * CO;
    float acc[2][8][4];
    gemm_mainloop<CO / 32>(Abase, CO, Bbase, CO, acc, tid);

    const int lane = tid & 31, warp = tid >> 5;
    const int wm = warp & 3, wn = warp >> 2;
    const int g = lane >> 2, t = lane & 3;
#pragma unroll
    for (int mt = 0; mt < 2; mt++)
#pragma unroll
        for (int h = 0; h < 2; h++) {
            int mloc = wm * 32 + mt * 16 + h * 8 + g;
            int o2 = o20 + mloc;
            float bv = sb2[mloc];
            const float* xrow = x + (size_t)b * CC * HW + (size_t)o2 * HW + s0;
            float* orow = out + (size_t)b * CC * HW + (size_t)o2 * HW + s0;
#pragma unroll
            for (int nt = 0; nt < 8; nt++) {
                int sc = wn * 64 + nt * 8 + t * 2;
                float2 xr = *(const float2*)(xrow + sc);
                float2 ov;
                ov.x = acc[mt][nt][h * 2 + 0] + bv + xr.x;
                ov.y = acc[mt][nt][h * 2 + 1] + bv + xr.y;
                *(float2*)(orow + sc) = ov;
            }
        }
}

// ---------------------------------------------------------------------------
extern "C" void kernel_launch(void* const* d_in, const int* in_sizes, int n_in,
                              void* d_out, int out_size) {
    const float* x    = (const float*)d_in[0];
    const float* emb  = (const float*)d_in[1];
    const float* gn_w = (const float*)d_in[2];
    const float* gn_b = (const float*)d_in[3];
    const float* w1   = (const float*)d_in[4];
    const float* b1   = (const float*)d_in[5];
    const float* we   = (const float*)d_in[6];
    const float* be   = (const float*)d_in[7];
    const float* w2   = (const float*)d_in[8];
    const float* b2   = (const float*)d_in[9];
    float* out = (float*)d_out;

    static bool attr_set = false;
    if (!attr_set) {
        cudaFuncSetAttribute(k_gemm1, cudaFuncAttributeMaxDynamicSharedMemorySize, SMEM1_BYTES);
        cudaFuncSetAttribute(k_gemm2, cudaFuncAttributeMaxDynamicSharedMemorySize, SMEM2_BYTES);
        attr_set = true;
    }

    k_setup<<<2048, 256>>>(x, gn_w, gn_b, emb, we, be, w1, w2);
    k_fold<<<1728, 256>>>(w1, b1, x);
    k_gemm1<<<dim3(HW / 128, CO / 128, BB), 256, SMEM1_BYTES>>>();
    k_gemm2<<<dim3(HW / 128, CC / 128, BB), 256, SMEM2_BYTES>>>(b2, x, out);
}

// round 14
// speedup vs baseline: 1.1564x; 1.0417x over previous
#include <cuda_runtime.h>
#include <cuda_fp16.h>
#include <cstdint>

// Problem constants
#define BB   16
#define CC   384      // C
#define CO   1536     // EXP*C
#define HW   1024     // 32*32
#define EMB_ 1024
#define NG   32
#define CPG  12
#define EPS_ 1e-5f

// ---------------- scratch (device globals) ---------------------------------
__device__ __align__(16) float  g_A[BB * CC];
__device__ __align__(16) float  g_D[BB * CC];
__device__ __align__(16) float  g_S[BB * CO];
__device__ __align__(16) float  g_T[BB * CO];
__device__ __align__(16) float  g_B1[BB * CO];                 // b1 + w1 @ D (fp32)
__device__ __align__(16) __half g_W1h[CO * CC];                // fp16 w1 [o][c]
__device__ __align__(16) __half g_W2h[CC * CO];                // fp16 w2 [o2][c']
__device__ __align__(16) __half g_Xh[(size_t)BB * CC * HW];    // fp16 a*x, NATURAL [b][c][s]
__device__ __align__(16) __half g_Hh[(size_t)BB * HW * CO];    // fp16 hidden [b][s][o]

// ---------------- helpers --------------------------------------------------
__device__ __forceinline__ void cpa16(uint32_t dst, const void* src) {
    asm volatile("cp.async.cg.shared.global [%0], [%1], 16;" :: "r"(dst), "l"(src));
}
#define CP_COMMIT() asm volatile("cp.async.commit_group;")
#define CP_WAIT1()  asm volatile("cp.async.wait_group 1;")

#define LDSM4(r0, r1, r2, r3, a)                                               \
    asm volatile("ldmatrix.sync.aligned.m8n8.x4.shared.b16 {%0,%1,%2,%3}, [%4];" \
        : "=r"(r0), "=r"(r1), "=r"(r2), "=r"(r3) : "r"(a))

#define LDSM4T(r0, r1, r2, r3, a)                                              \
    asm volatile("ldmatrix.sync.aligned.m8n8.x4.trans.shared.b16 {%0,%1,%2,%3}, [%4];" \
        : "=r"(r0), "=r"(r1), "=r"(r2), "=r"(r3) : "r"(a))

#define MMA_F16(d, a, b)                                                       \
    asm volatile(                                                              \
        "mma.sync.aligned.m16n8k16.row.col.f32.f16.f16.f32 "                   \
        "{%0,%1,%2,%3},{%4,%5,%6,%7},{%8,%9},{%0,%1,%2,%3};\n"                 \
        : "+f"((d)[0]), "+f"((d)[1]), "+f"((d)[2]), "+f"((d)[3])               \
        : "r"((a)[0]), "r"((a)[1]), "r"((a)[2]), "r"((a)[3]),                  \
          "r"((b)[0]), "r"((b)[1]))

// ---------------------------------------------------------------------------
// K_setup: FUSED gnstats + emb + w->fp16 prep (proven config).
// ---------------------------------------------------------------------------
__global__ void __launch_bounds__(256)
k_setup(const float* __restrict__ x,
        const float* __restrict__ gnw,
        const float* __restrict__ gnb,
        const float* __restrict__ emb,
        const float* __restrict__ we,
        const float* __restrict__ be,
        const float* __restrict__ w1,
        const float* __restrict__ w2) {
    int bid = blockIdx.x;
    if (bid < 512) {
        int b = bid >> 5;
        int gi = bid & 31;
        const float4* p = (const float4*)(x + ((size_t)b * CC + (size_t)gi * CPG) * HW);
        float s = 0.f, ss = 0.f;
#pragma unroll
        for (int i = 0; i < 12; i++) {
            float4 v = p[threadIdx.x + i * 256];
            s  += v.x + v.y + v.z + v.w;
            ss += v.x * v.x + v.y * v.y + v.z * v.z + v.w * v.w;
        }
#pragma unroll
        for (int off = 16; off; off >>= 1) {
            s  += __shfl_xor_sync(0xffffffffu, s, off);
            ss += __shfl_xor_sync(0xffffffffu, ss, off);
        }
        __shared__ float sh[64];
        int w = threadIdx.x >> 5, l = threadIdx.x & 31;
        if (l == 0) { sh[w] = s; sh[32 + w] = ss; }
        __syncthreads();
        if (threadIdx.x < CPG) {
            float S = 0.f, SS = 0.f;
#pragma unroll
            for (int i = 0; i < 8; i++) { S += sh[i]; SS += sh[32 + i]; }
            float mean = S * (1.0f / 12288.0f);
            float var  = SS * (1.0f / 12288.0f) - mean * mean;
            float rstd = rsqrtf(var + EPS_);
            int cch = gi * CPG + threadIdx.x;
            float wv = gnw[cch], bv = gnb[cch];
            g_A[b * CC + cch] = rstd * wv;
            g_D[b * CC + cch] = bv - mean * rstd * wv;
        }
    } else if (bid < 896) {
        int o = (bid - 512) * 8 + (threadIdx.x >> 5);   // 0..3071
        int lane = threadIdx.x & 31;
        const float4* w4 = (const float4*)(we + (size_t)o * EMB_);
        float4 wv[8];
#pragma unroll
        for (int i = 0; i < 8; i++) wv[i] = w4[lane + i * 32];
        float bev = be[o];

        float mine = 0.f;
#pragma unroll
        for (int b = 0; b < BB; b++) {
            const float4* e4 = (const float4*)(emb + (size_t)b * EMB_);
            float s = 0.f;
#pragma unroll
            for (int i = 0; i < 8; i++) {
                float4 ev = e4[lane + i * 32];
                s += ev.x * wv[i].x + ev.y * wv[i].y + ev.z * wv[i].z + ev.w * wv[i].w;
            }
#pragma unroll
            for (int off = 16; off; off >>= 1)
                s += __shfl_xor_sync(0xffffffffu, s, off);
            if (lane == b) mine = s;
        }
        if (lane < BB) {
            if (o < CO) g_S[lane * CO + o] = 1.0f + mine + bev;
            else        g_T[lane * CO + (o - CO)] = mine + bev;
        }
    } else {
        const int N1 = CO * CC / 4;
        int t = (bid - 896) * 256 + threadIdx.x;
        const float4* src = (t < N1) ? (const float4*)w1 : (const float4*)w2;
        int i = (t < N1) ? t : t - N1;
        float4 v = src[i];
        __half2 lo = __floats2half2_rn(v.x, v.y);
        __half2 hi = __floats2half2_rn(v.z, v.w);
        uint2 pk = make_uint2(*(uint32_t*)&lo, *(uint32_t*)&hi);
        if (t < N1) ((uint2*)g_W1h)[i] = pk;
        else        ((uint2*)g_W2h)[i] = pk;
    }
}

// ---------------------------------------------------------------------------
// K_fold: bias-fold b1' = b1 + w1@D, plus streaming xh = fp16(A*x).
// ---------------------------------------------------------------------------
__global__ void __launch_bounds__(256)
k_fold(const float* __restrict__ w1,
       const float* __restrict__ b1,
       const float* __restrict__ x) {
    int bid = blockIdx.x;
    if (bid < 192) {
        int o = bid * 8 + (threadIdx.x >> 5);       // 0..1535
        int lane = threadIdx.x & 31;
        const float4* w4 = (const float4*)(w1 + (size_t)o * CC);
        float4 wv[3];
#pragma unroll
        for (int i = 0; i < 3; i++) wv[i] = w4[lane + i * 32];
        float bv = b1[o];
        float mine = 0.f;
#pragma unroll
        for (int b = 0; b < BB; b++) {
            const float* dr = g_D + b * CC;
            float s = 0.f;
#pragma unroll
            for (int i = 0; i < 3; i++) {
                int c = (lane + i * 32) * 4;
                s += wv[i].x * dr[c] + wv[i].y * dr[c + 1]
                   + wv[i].z * dr[c + 2] + wv[i].w * dr[c + 3];
            }
#pragma unroll
            for (int off = 16; off; off >>= 1)
                s += __shfl_xor_sync(0xffffffffu, s, off);
            if (lane == b) mine = s;
        }
        if (lane < BB) g_B1[lane * CO + o] = bv + mine;
    } else {
        int base = (bid - 192) * 1024 + threadIdx.x;
#pragma unroll
        for (int i = 0; i < 4; i++) {
            int idx = base + i * 256;               // float4 index
            float a = g_A[idx >> 8];
            float4 v = ((const float4*)x)[idx];
            __half2 lo = __floats2half2_rn(a * v.x, a * v.y);
            __half2 hi = __floats2half2_rn(a * v.z, a * v.w);
            ((uint2*)g_Xh)[idx] = make_uint2(*(uint32_t*)&lo, *(uint32_t*)&hi);
        }
    }
}

// ---------------------------------------------------------------------------
// GEMM geometry: CTA tile 128x128, BK=64 halves, NSTAGE=3 cp.async ring.
// One barrier per k-tile:  CP_WAIT1 -> __syncthreads -> fill((kt+2)%3)
//   -> commit -> compute(kt%3)
// RAW: commits before wait = 2+kt; pending<=1 => stage kt landed (thread);
//      barrier publishes. WAR: fill target (kt+2)%3=(kt-1)%3, readers done.
// Bytes in flight ~72KB (>= R9's 60KB), barriers halved vs BK=32.
// Pitch 144B (36 words): ldmatrix rows 4r mod 32 -> 8 distinct bank-quads.
// ---------------------------------------------------------------------------
#define PITCH   144
#define TILE_K64 (128 * PITCH)          // 18432 B: 128 rows x 64 halves
#define STG2_B  (2 * TILE_K64)          // 36864 B
#define NSTAGE  3
#define SMEM2_BYTES (NSTAGE * STG2_B)   // 110592 B

// gemm1 A-tile (trans): 64 k-rows x 128 s-halves (256B data), pitch 272
#define PITCH_A1 272
#define TILE_A1  (64 * PITCH_A1)        // 17408 B
#define STG1_B   (TILE_A1 + TILE_K64)   // 35840 B
#define SMEM1_BYTES (NSTAGE * STG1_B)   // 107520 B

extern __shared__ uint8_t dsm8[];

// ---- gemm2 fill: both operands K-major, 128 rows x 128B data ----
__device__ __forceinline__ void fill_g2(uint32_t sdst,
        const __half* Asrc, const __half* Bsrc, int tid) {
#pragma unroll
    for (int i = 0; i < 8; i++) {
        int ch = tid + i * 256;            // 0..2047
        int isB = ch >> 10;
        int base = ch & 1023;
        int r = base >> 3, cb = base & 7;
        const __half* src = isB ? (Bsrc + (size_t)r * CO + cb * 8)
                                : (Asrc + (size_t)r * CO + cb * 8);
        cpa16(sdst + isB * TILE_K64 + r * PITCH + cb * 16, src);
    }
}

// ---- gemm1 fill: A = xh trans tile (64 rows x 256B), B = w1 K-major ----
__device__ __forceinline__ void fill_g1(uint32_t sdst,
        const __half* Ax, const __half* Bw, int tid) {
#pragma unroll
    for (int i = 0; i < 8; i++) {
        int ch = tid + i * 256;            // 0..2047
        if (ch < 1024) {                   // A: 64 rows x 16 chunks
            int r = ch >> 4, cb = ch & 15;
            cpa16(sdst + r * PITCH_A1 + cb * 16, Ax + (size_t)r * HW + cb * 8);
        } else {                           // B: 128 rows x 8 chunks
            int base = ch - 1024;
            int r = base >> 3, cb = base & 7;
            cpa16(sdst + TILE_A1 + r * PITCH + cb * 16,
                  Bw + (size_t)r * CC + cb * 8);
        }
    }
}

// ---------------------------------------------------------------------------
// K_gemm1: D[s,o] = xh^T @ w1^T via trans-ldmatrix A. K=CC, KT=6.
// ---------------------------------------------------------------------------
__global__ void __launch_bounds__(256, 2)
k_gemm1() {
    __shared__ float sb1[128], sS[128], sT[128];
    const int tid = threadIdx.x;
    const int b = blockIdx.z;
    const int o0 = blockIdx.y * 128;
    const int s0 = blockIdx.x * 128;
    if (tid < 128) {
        int o = o0 + tid;
        sb1[tid] = g_B1[b * CO + o];
        sS[tid]  = g_S[b * CO + o];
        sT[tid]  = g_T[b * CO + o];
    }
    __syncthreads();

    const __half* Abase = g_Xh + (size_t)b * CC * HW + s0;
    const __half* Bbase = g_W1h + (size_t)o0 * CC;

    const int lane = tid & 31, warp = tid >> 5;
    const int wm = warp & 3, wn = warp >> 2;
    float acc[2][8][4];
#pragma unroll
    for (int i = 0; i < 2; i++)
#pragma unroll
        for (int j = 0; j < 8; j++)
#pragma unroll
            for (int e = 0; e < 4; e++) acc[i][j][e] = 0.f;

    uint32_t smb = (uint32_t)__cvta_generic_to_shared(dsm8);
    uint32_t aoff = (uint32_t)(((lane & 7) + ((lane >> 4) << 3)) * PITCH_A1
                               + ((lane >> 3) & 1) * 16);
    uint32_t boff = (uint32_t)((wn * 64 + (lane & 7) + ((lane >> 4) << 3)) * PITCH
                               + ((lane >> 3) & 1) * 16);

    const int KT = CC / 64;   // 6
#pragma unroll
    for (int s = 0; s < NSTAGE - 1; s++) {
        fill_g1(smb + s * STG1_B, Abase + (size_t)s * 64 * HW, Bbase + s * 64, tid);
        CP_COMMIT();
    }

    int s_cur = 0, s_fill = NSTAGE - 1;
    for (int kt = 0; kt < KT; kt++) {
        CP_WAIT1();
        __syncthreads();

        if (kt + NSTAGE - 1 < KT)
            fill_g1(smb + s_fill * STG1_B,
                    Abase + (size_t)(kt + NSTAGE - 1) * 64 * HW,
                    Bbase + (size_t)(kt + NSTAGE - 1) * 64, tid);
        CP_COMMIT();

        uint32_t sA = smb + s_cur * STG1_B;
        uint32_t sB = sA + TILE_A1;
#pragma unroll
        for (int kk = 0; kk < 4; kk++) {           // four k16 chunks of BK=64
            uint32_t af[2][4], bf[8][2];
#pragma unroll
            for (int mt = 0; mt < 2; mt++)
                LDSM4T(af[mt][0], af[mt][1], af[mt][2], af[mt][3],
                       sA + aoff + kk * 16 * PITCH_A1 + (wm * 32 + mt * 16) * 2);
#pragma unroll
            for (int p = 0; p < 4; p++) {
                uint32_t r0, r1, r2, r3;
                LDSM4(r0, r1, r2, r3, sB + boff + p * 16 * PITCH + kk * 32);
                bf[2 * p][0] = r0;  bf[2 * p][1] = r1;
                bf[2 * p + 1][0] = r2; bf[2 * p + 1][1] = r3;
            }
#pragma unroll
            for (int mt = 0; mt < 2; mt++)
#pragma unroll
                for (int nt = 0; nt < 8; nt++)
                    MMA_F16(acc[mt][nt], af[mt], bf[nt]);
        }
        s_cur  = (s_cur  == NSTAGE - 1) ? 0 : s_cur + 1;
        s_fill = (s_fill == NSTAGE - 1) ? 0 : s_fill + 1;
    }

    const int g = lane >> 2, t = lane & 3;
    __half* Hb = g_Hh + ((size_t)b * HW + s0) * CO + o0;
#pragma unroll
    for (int mt = 0; mt < 2; mt++)
#pragma unroll
        for (int h = 0; h < 2; h++) {
            int s_loc = wm * 32 + mt * 16 + h * 8 + g;
            __half* Hrow = Hb + (size_t)s_loc * CO;
#pragma unroll
            for (int nt = 0; nt < 8; nt++) {
                int oc = wn * 64 + nt * 8 + t * 2;
                float v0 = acc[mt][nt][h * 2 + 0] + sb1[oc];
                float v1 = acc[mt][nt][h * 2 + 1] + sb1[oc + 1];
                float h0 = v0 / (1.0f + __expf(-v0));
                float h1 = v1 / (1.0f + __expf(-v1));
                __half2 pk = __floats2half2_rn(h0 * sS[oc] + sT[oc],
                                               h1 * sS[oc + 1] + sT[oc + 1]);
                *(uint32_t*)(Hrow + oc) = *(uint32_t*)&pk;
            }
        }
}

// ---------------------------------------------------------------------------
// K_gemm2: D[o2,s] = w2 @ H^T; K=CO, KT=24. Tile/warp geometry = measured
// best (128x128 / 32x64); only the ring is BK=64/3-stage now.
// ---------------------------------------------------------------------------
__global__ void __launch_bounds__(256, 2)
k_gemm2(const float* __restrict__ b2,
        const float* __restrict__ x,
        float* __restrict__ out) {
    __shared__ float sb2[128];
    const int tid = threadIdx.x;
    const int b = blockIdx.z;
    const int o20 = blockIdx.y * 128;
    const int s0 = blockIdx.x * 128;
    if (tid < 128) sb2[tid] = b2[o20 + tid];
    __syncthreads();

    const __half* Abase = g_W2h + (size_t)o20 * CO;
    const __half* Bbase = g_Hh + ((size_t)b * HW + s0) * CO;

    const int lane = tid & 31, warp = tid >> 5;
    const int wm = warp & 3, wn = warp >> 2;
    float acc[2][8][4];
#pragma unroll
    for (int i = 0; i < 2; i++)
#pragma unroll
        for (int j = 0; j < 8; j++)
#pragma unroll
            for (int e = 0; e < 4; e++) acc[i][j][e] = 0.f;

    uint32_t smb = (uint32_t)__cvta_generic_to_shared(dsm8);
    uint32_t aoff = (uint32_t)((wm * 32 + (lane & 15)) * PITCH + (lane >> 4) * 16);
    uint32_t boff = (uint32_t)((wn * 64 + (lane & 7) + ((lane >> 4) << 3)) * PITCH
                               + ((lane >> 3) & 1) * 16);

    const int KT = CO / 64;   // 24
#pragma unroll
    for (int s = 0; s < NSTAGE - 1; s++) {
        fill_g2(smb + s * STG2_B, Abase + s * 64, Bbase + s * 64, tid);
        CP_COMMIT();
    }

    int s_cur = 0, s_fill = NSTAGE - 1;
    for (int kt = 0; kt < KT; kt++) {
        CP_WAIT1();
        __syncthreads();

        if (kt + NSTAGE - 1 < KT)
            fill_g2(smb + s_fill * STG2_B,
                    Abase + (size_t)(kt + NSTAGE - 1) * 64,
                    Bbase + (size_t)(kt + NSTAGE - 1) * 64, tid);
        CP_COMMIT();

        uint32_t sA = smb + s_cur * STG2_B;
        uint32_t sB = sA + TILE_K64;
#pragma unroll
        for (int kk = 0; kk < 4; kk++) {
            uint32_t af[2][4], bf[8][2];
#pragma unroll
            for (int mt = 0; mt < 2; mt++)
                LDSM4(af[mt][0], af[mt][1], af[mt][2], af[mt][3],
                      sA + aoff + mt * 16 * PITCH + kk * 32);
#pragma unroll
            for (int p = 0; p < 4; p++) {
                uint32_t r0, r1, r2, r3;
                LDSM4(r0, r1, r2, r3, sB + boff + p * 16 * PITCH + kk * 32);
                bf[2 * p][0] = r0;  bf[2 * p][1] = r1;
                bf[2 * p + 1][0] = r2; bf[2 * p + 1][1] = r3;
            }
#pragma unroll
            for (int mt = 0; mt < 2; mt++)
#pragma unroll
                for (int nt = 0; nt < 8; nt++)
                    MMA_F16(acc[mt][nt], af[mt], bf[nt]);
        }
        s_cur  = (s_cur  == NSTAGE - 1) ? 0 : s_cur + 1;
        s_fill = (s_fill == NSTAGE - 1) ? 0 : s_fill + 1;
    }

    const int g = lane >> 2, t = lane & 3;
#pragma unroll
    for (int mt = 0; mt < 2; mt++)
#pragma unroll
        for (int h = 0; h < 2; h++) {
            int mloc = wm * 32 + mt * 16 + h * 8 + g;
            int o2 = o20 + mloc;
            float bv = sb2[mloc];
            const float* xrow = x + (size_t)b * CC * HW + (size_t)o2 * HW + s0;
            float* orow = out + (size_t)b * CC * HW + (size_t)o2 * HW + s0;
#pragma unroll
            for (int nt = 0; nt < 8; nt++) {
                int sc = wn * 64 + nt * 8 + t * 2;
                float2 xr = *(const float2*)(xrow + sc);
                float2 ov;
                ov.x = acc[mt][nt][h * 2 + 0] + bv + xr.x;
                ov.y = acc[mt][nt][h * 2 + 1] + bv + xr.y;
                *(float2*)(orow + sc) = ov;
            }
        }
}

// ---------------------------------------------------------------------------
extern "C" void kernel_launch(void* const* d_in, const int* in_sizes, int n_in,
                              void* d_out, int out_size) {
    const float* x    = (const float*)d_in[0];
    const float* emb  = (const float*)d_in[1];
    const float* gn_w = (const float*)d_in[2];
    const float* gn_b = (const float*)d_in[3];
    const float* w1   = (const float*)d_in[4];
    const float* b1   = (const float*)d_in[5];
    const float* we   = (const float*)d_in[6];
    const float* be   = (const float*)d_in[7];
    const float* w2   = (const float*)d_in[8];
    const float* b2   = (const float*)d_in[9];
    float* out = (float*)d_out;

    static bool attr_set = false;
    if (!attr_set) {
        cudaFuncSetAttribute(k_gemm1, cudaFuncAttributeMaxDynamicSharedMemorySize, SMEM1_BYTES);
        cudaFuncSetAttribute(k_gemm2, cudaFuncAttributeMaxDynamicSharedMemorySize, SMEM2_BYTES);
        attr_set = true;
    }

    k_setup<<<2048, 256>>>(x, gn_w, gn_b, emb, we, be, w1, w2);
    k_fold<<<1728, 256>>>(w1, b1, x);
    k_gemm1<<<dim3(HW / 128, CO / 128, BB), 256, SMEM1_BYTES>>>();
    k_gemm2<<<dim3(HW / 128, CC / 128, BB), 256, SMEM2_BYTES>>>(b2, x, out);
}